// round 16
// baseline (speedup 1.0000x reference)
#include <cuda_runtime.h>
#include <cuda_bf16.h>
#include <cstdint>
#include <math_constants.h>

#define NTOK 4096
#define DIN  1024
#define DH   512

// ---------------------------------------------------------------------------
// Scratch (__device__ globals; no allocation allowed)
// ---------------------------------------------------------------------------
__device__ __nv_bfloat16 g_Eh[(size_t)NTOK * DIN];
__device__ __nv_bfloat16 g_El[(size_t)NTOK * DIN];
__device__ __nv_bfloat16 g_Wqh[(size_t)DH * DIN];
__device__ __nv_bfloat16 g_Wql[(size_t)DH * DIN];
__device__ __nv_bfloat16 g_Wkh[(size_t)DH * DIN];
__device__ __nv_bfloat16 g_Wkl[(size_t)DH * DIN];
__device__ __nv_bfloat16 g_Wvh[(size_t)DH * DIN];
__device__ __nv_bfloat16 g_Wvl[(size_t)DH * DIN];
__device__ __nv_bfloat16 g_Qh[(size_t)NTOK * DH];
__device__ __nv_bfloat16 g_Ql[(size_t)NTOK * DH];
__device__ __nv_bfloat16 g_Kh[(size_t)NTOK * DH];
__device__ __nv_bfloat16 g_Kl[(size_t)NTOK * DH];
__device__ __nv_bfloat16 g_VtH[(size_t)DH * NTOK];
__device__ __nv_bfloat16 g_VtL[(size_t)DH * NTOK];
__device__ float         g_S[(size_t)NTOK * NTOK];
__device__ __nv_bfloat16 g_Ph[(size_t)NTOK * NTOK];
__device__ __nv_bfloat16 g_Pl[(size_t)NTOK * NTOK];

// ---------------------------------------------------------------------------
// PTX helpers (sm_80-level: valid under compute_103 virtual arch)
// ---------------------------------------------------------------------------
__device__ __forceinline__ uint32_t smem_u32(const void* p) {
    uint32_t a;
    asm("{ .reg .u64 t; cvta.to.shared.u64 t, %1; cvt.u32.u64 %0, t; }"
        : "=r"(a) : "l"(p));
    return a;
}

__device__ __forceinline__ void cp16(uint32_t dst, const void* src) {
    asm volatile("cp.async.cg.shared.global [%0], [%1], 16;"
                 :: "r"(dst), "l"(src) : "memory");
}
#define CP_COMMIT() asm volatile("cp.async.commit_group;" ::: "memory")
#define CP_WAIT(n)  asm volatile("cp.async.wait_group %0;" :: "n"(n) : "memory")

#define LDSM4(r0, r1, r2, r3, addr)                                            \
    asm volatile("ldmatrix.sync.aligned.m8n8.x4.shared.b16 {%0,%1,%2,%3}, [%4];" \
                 : "=r"(r0), "=r"(r1), "=r"(r2), "=r"(r3) : "r"(addr))

#define MMA_BF16(c, a, b0, b1)                                                 \
    asm volatile("mma.sync.aligned.m16n8k16.row.col.f32.bf16.bf16.f32 "        \
                 "{%0,%1,%2,%3}, {%4,%5,%6,%7}, {%8,%9}, {%0,%1,%2,%3};"       \
                 : "+f"((c)[0]), "+f"((c)[1]), "+f"((c)[2]), "+f"((c)[3])      \
                 : "r"((a)[0]), "r"((a)[1]), "r"((a)[2]), "r"((a)[3]),         \
                   "r"(b0), "r"(b1))

__device__ __forceinline__ uint32_t sw(uint32_t off) {
    return off ^ ((off >> 3) & 0x70);
}

// ---------------------------------------------------------------------------
// hi/lo split conversion (fp32 -> bf16 hi + bf16 lo), one z-indexed launch
// ---------------------------------------------------------------------------
__device__ __forceinline__ void split4(float4 v, __nv_bfloat162* h, __nv_bfloat162* l,
                                       int i)
{
    __nv_bfloat16 hx = __float2bfloat16(v.x);
    __nv_bfloat16 hy = __float2bfloat16(v.y);
    __nv_bfloat16 hz = __float2bfloat16(v.z);
    __nv_bfloat16 hw = __float2bfloat16(v.w);
    h[2 * i + 0] = __nv_bfloat162(hx, hy);
    h[2 * i + 1] = __nv_bfloat162(hz, hw);
    l[2 * i + 0] = __nv_bfloat162(__float2bfloat16(v.x - __bfloat162float(hx)),
                                  __float2bfloat16(v.y - __bfloat162float(hy)));
    l[2 * i + 1] = __nv_bfloat162(__float2bfloat16(v.z - __bfloat162float(hz)),
                                  __float2bfloat16(v.w - __bfloat162float(hw)));
}

__global__ void split_all(const float4* __restrict__ embs,
                          const float4* __restrict__ Wq,
                          const float4* __restrict__ Wk,
                          const float4* __restrict__ Wv,
                          __nv_bfloat162* __restrict__ eh, __nv_bfloat162* __restrict__ el,
                          __nv_bfloat162* __restrict__ qh, __nv_bfloat162* __restrict__ ql,
                          __nv_bfloat162* __restrict__ kh, __nv_bfloat162* __restrict__ kl,
                          __nv_bfloat162* __restrict__ vh, __nv_bfloat162* __restrict__ vl)
{
    const int z = blockIdx.z;
    const float4* x;
    __nv_bfloat162 *h, *l;
    int n4;
    if (z == 0)      { x = embs; h = eh; l = el; n4 = NTOK * DIN / 4; }
    else if (z == 1) { x = Wq;   h = qh; l = ql; n4 = DH * DIN / 4; }
    else if (z == 2) { x = Wk;   h = kh; l = kl; n4 = DH * DIN / 4; }
    else             { x = Wv;   h = vh; l = vl; n4 = DH * DIN / 4; }
    for (int i = blockIdx.x * blockDim.x + threadIdx.x; i < n4;
         i += gridDim.x * blockDim.x)
        split4(x[i], h, l, i);
}

// ---------------------------------------------------------------------------
// GEMM body: C = Ah·Bh^T + Ah·Bl^T + Al·Bh^T over K from kbase.
// 3-stage cp.async pipeline, ONE __syncthreads per chunk, register
// double-buffered fragments. CTA 128x128, 8 warps (4x2), warp tile 32x64.
// epi: 0 = fp32 C, 1 = split (Ch,Cl) [M,N],
//      2 = split transposed [N,M] via SMEM-staged transpose (coalesced)
// ---------------------------------------------------------------------------
#define KCH 64
#define TILE_BYTES  16384          // 128 rows x 128B
#define STAGE_BYTES 65536          // Ah | Al | Bh | Bl
#define NSTAGE 3
#define SMEM_BYTES  (NSTAGE * STAGE_BYTES)   // 192 KB
#define TPAD 136                   // padded row stride for transpose staging

__device__ __forceinline__ void load_tile(uint32_t sbase, const __nv_bfloat16* g,
                                          int ld, int row0, int k0, int tid)
{
    const char* gp = (const char*)(g + (size_t)row0 * ld + k0);
    size_t ldb = (size_t)ld * 2;
    #pragma unroll
    for (int i = 0; i < 4; i++) {
        int idx = tid + i * 256;
        int r = idx >> 3, j = idx & 7;
        uint32_t off = (uint32_t)(r * 128 + j * 16);
        cp16(sbase + sw(off), gp + (size_t)r * ldb + j * 16);
    }
}

__device__ __forceinline__ void gemm3x_body(
    const __nv_bfloat16* __restrict__ Ah, const __nv_bfloat16* __restrict__ Al,
    const __nv_bfloat16* __restrict__ Bh, const __nv_bfloat16* __restrict__ Bl,
    const float* __restrict__ bias,
    float* __restrict__ Cf,
    __nv_bfloat16* __restrict__ Ch, __nv_bfloat16* __restrict__ Cl,
    int M, int N, int K, int ldA, int ldB, int kbase, int epi, char* smem)
{
    const uint32_t sb = smem_u32(smem);

    const int tid  = threadIdx.x;
    const int wid  = tid >> 5;
    const int lane = tid & 31;
    const int wm   = wid >> 1;          // 0..3
    const int wn   = wid & 1;           // 0..1
    const int bm   = blockIdx.y * 128;
    const int bn   = blockIdx.x * 128;

    float acc[2][8][4];
    #pragma unroll
    for (int i = 0; i < 2; i++)
        #pragma unroll
        for (int j = 0; j < 8; j++)
            #pragma unroll
            for (int t = 0; t < 4; t++) acc[i][j][t] = 0.0f;

    const int KC = K / KCH;

    const int a_row = wm * 32 + (lane & 15);
    const int a_seg = (lane >> 4);
    const int b_row = wn * 64 + (lane & 7) + ((lane >> 4) << 3);
    const int b_seg = ((lane >> 3) & 1);

    auto load_chunk = [&](uint32_t stg, int c) {
        const int k0 = kbase + c * KCH;
        load_tile(stg,                  Ah, ldA, bm, k0, tid);
        load_tile(stg + TILE_BYTES,     Al, ldA, bm, k0, tid);
        load_tile(stg + 2 * TILE_BYTES, Bh, ldB, bn, k0, tid);
        load_tile(stg + 3 * TILE_BYTES, Bl, ldB, bn, k0, tid);
    };

    // prologue: 2 chunks in flight
    load_chunk(sb, 0);
    CP_COMMIT();
    if (KC > 1) load_chunk(sb + STAGE_BYTES, 1);
    CP_COMMIT();

    // Double-buffered fragments
    uint32_t aH[2][2][4], aL[2][2][4], bHf[2][4][4], bLf[2][4][4];

    for (int c = 0; c < KC; c++) {
        if (c + 1 < KC) { CP_WAIT(1); } else { CP_WAIT(0); }
        __syncthreads();    // stage c%3 ready; everyone done reading stage (c+2)%3

        // loads for chunk c+2 into stage (c+2)%3 — overlap the MMAs below
        if (c + 2 < KC)
            load_chunk(sb + (uint32_t)((c + 2) % NSTAGE) * STAGE_BYTES, c + 2);
        CP_COMMIT();

        const uint32_t stg = sb + (uint32_t)(c % NSTAGE) * STAGE_BYTES;
        const uint32_t saH = stg;
        const uint32_t saL = stg + TILE_BYTES;
        const uint32_t sbH = stg + 2 * TILE_BYTES;
        const uint32_t sbL = stg + 3 * TILE_BYTES;

        // preload ks=0 fragments into buffer 0
        {
            #pragma unroll
            for (int mi = 0; mi < 2; mi++) {
                uint32_t so = sw((uint32_t)((a_row + mi * 16) * 128 + a_seg * 16));
                LDSM4(aH[0][mi][0], aH[0][mi][1], aH[0][mi][2], aH[0][mi][3], saH + so);
                LDSM4(aL[0][mi][0], aL[0][mi][1], aL[0][mi][2], aL[0][mi][3], saL + so);
            }
            #pragma unroll
            for (int ng = 0; ng < 4; ng++) {
                uint32_t so = sw((uint32_t)((b_row + ng * 16) * 128 + b_seg * 16));
                LDSM4(bHf[0][ng][0], bHf[0][ng][1], bHf[0][ng][2], bHf[0][ng][3], sbH + so);
                LDSM4(bLf[0][ng][0], bLf[0][ng][1], bLf[0][ng][2], bLf[0][ng][3], sbL + so);
            }
        }

        #pragma unroll
        for (int ks = 0; ks < 4; ks++) {
            const int cur = ks & 1;
            const int nxt = cur ^ 1;
            if (ks < 3) {
                // issue next ks's LDSMs before this ks's MMAs
                #pragma unroll
                for (int mi = 0; mi < 2; mi++) {
                    uint32_t so = sw((uint32_t)((a_row + mi * 16) * 128 +
                                                ((ks + 1) * 2 + a_seg) * 16));
                    LDSM4(aH[nxt][mi][0], aH[nxt][mi][1], aH[nxt][mi][2], aH[nxt][mi][3],
                          saH + so);
                    LDSM4(aL[nxt][mi][0], aL[nxt][mi][1], aL[nxt][mi][2], aL[nxt][mi][3],
                          saL + so);
                }
                #pragma unroll
                for (int ng = 0; ng < 4; ng++) {
                    uint32_t so = sw((uint32_t)((b_row + ng * 16) * 128 +
                                                ((ks + 1) * 2 + b_seg) * 16));
                    LDSM4(bHf[nxt][ng][0], bHf[nxt][ng][1], bHf[nxt][ng][2], bHf[nxt][ng][3],
                          sbH + so);
                    LDSM4(bLf[nxt][ng][0], bLf[nxt][ng][1], bLf[nxt][ng][2], bLf[nxt][ng][3],
                          sbL + so);
                }
            }
            #pragma unroll
            for (int mi = 0; mi < 2; mi++)
                #pragma unroll
                for (int nj = 0; nj < 8; nj++) {
                    const int ng = nj >> 1, hp = (nj & 1) << 1;
                    MMA_BF16(acc[mi][nj], aH[cur][mi], bHf[cur][ng][hp], bHf[cur][ng][hp + 1]);
                }
            #pragma unroll
            for (int mi = 0; mi < 2; mi++)
                #pragma unroll
                for (int nj = 0; nj < 8; nj++) {
                    const int ng = nj >> 1, hp = (nj & 1) << 1;
                    MMA_BF16(acc[mi][nj], aH[cur][mi], bLf[cur][ng][hp], bLf[cur][ng][hp + 1]);
                }
            #pragma unroll
            for (int mi = 0; mi < 2; mi++)
                #pragma unroll
                for (int nj = 0; nj < 8; nj++) {
                    const int ng = nj >> 1, hp = (nj & 1) << 1;
                    MMA_BF16(acc[mi][nj], aL[cur][mi], bHf[cur][ng][hp], bHf[cur][ng][hp + 1]);
                }
        }
        // no trailing sync: next iteration's top sync protects stage reuse
    }

    // ---------------- epilogue ----------------
    const int r0  = (lane >> 2);
    const int cth = 2 * (lane & 3);

    if (epi == 2) {
        // SMEM-staged transpose with bias applied BEFORE staging.
        __syncthreads();   // all warps done reading pipeline SMEM
        __nv_bfloat16* sH = (__nv_bfloat16*)smem;
        __nv_bfloat16* sL = sH + 128 * TPAD;
        #pragma unroll
        for (int mi = 0; mi < 2; mi++) {
            #pragma unroll
            for (int nj = 0; nj < 8; nj++) {
                const int c0 = wn * 64 + nj * 8 + cth;     // tile-local col
                const int rA = wm * 32 + mi * 16 + r0;     // tile-local row
                const int rB = rA + 8;
                float v0 = acc[mi][nj][0], v1 = acc[mi][nj][1];
                float v2 = acc[mi][nj][2], v3 = acc[mi][nj][3];
                if (bias) {
                    float b0 = bias[bn + c0], b1 = bias[bn + c0 + 1];
                    v0 += b0; v1 += b1; v2 += b0; v3 += b1;
                }
                __nv_bfloat16 h0 = __float2bfloat16(v0);
                __nv_bfloat16 h1 = __float2bfloat16(v1);
                __nv_bfloat16 h2 = __float2bfloat16(v2);
                __nv_bfloat16 h3 = __float2bfloat16(v3);
                sH[c0 * TPAD + rA]       = h0;
                sH[(c0 + 1) * TPAD + rA] = h1;
                sH[c0 * TPAD + rB]       = h2;
                sH[(c0 + 1) * TPAD + rB] = h3;
                sL[c0 * TPAD + rA]       = __float2bfloat16(v0 - __bfloat162float(h0));
                sL[(c0 + 1) * TPAD + rA] = __float2bfloat16(v1 - __bfloat162float(h1));
                sL[c0 * TPAD + rB]       = __float2bfloat16(v2 - __bfloat162float(h2));
                sL[(c0 + 1) * TPAD + rB] = __float2bfloat16(v3 - __bfloat162float(h3));
            }
        }
        __syncthreads();
        // copy out: 128 cols x 128 rows = 2048 uint4 per plane; 8 per thread
        #pragma unroll
        for (int i = 0; i < 8; i++) {
            int idx = tid + i * 256;        // 0..2047
            int c0 = idx >> 4;              // 0..127
            int j  = idx & 15;              // 16B segment within the 256B row
            uint4 vh = *(uint4*)&sH[c0 * TPAD + j * 8];
            uint4 vl = *(uint4*)&sL[c0 * TPAD + j * 8];
            size_t base = (size_t)(bn + c0) * M + bm + j * 8;
            *(uint4*)&Ch[base] = vh;
            *(uint4*)&Cl[base] = vl;
        }
        return;
    }

    #pragma unroll
    for (int mi = 0; mi < 2; mi++) {
        #pragma unroll
        for (int nj = 0; nj < 8; nj++) {
            const int col = bn + wn * 64 + nj * 8 + cth;
            float v0 = acc[mi][nj][0], v1 = acc[mi][nj][1];
            float v2 = acc[mi][nj][2], v3 = acc[mi][nj][3];
            if (bias) {
                float b0 = bias[col], b1 = bias[col + 1];
                v0 += b0; v1 += b1; v2 += b0; v3 += b1;
            }
            const int rowA = bm + wm * 32 + mi * 16 + r0;
            const int rowB = rowA + 8;
            if (epi == 0) {
                *(float2*)&Cf[(size_t)rowA * N + col] = make_float2(v0, v1);
                *(float2*)&Cf[(size_t)rowB * N + col] = make_float2(v2, v3);
            } else {
                __nv_bfloat16 h0 = __float2bfloat16(v0);
                __nv_bfloat16 h1 = __float2bfloat16(v1);
                __nv_bfloat16 h2 = __float2bfloat16(v2);
                __nv_bfloat16 h3 = __float2bfloat16(v3);
                *(__nv_bfloat162*)&Ch[(size_t)rowA * N + col] = __nv_bfloat162(h0, h1);
                *(__nv_bfloat162*)&Ch[(size_t)rowB * N + col] = __nv_bfloat162(h2, h3);
                *(__nv_bfloat162*)&Cl[(size_t)rowA * N + col] = __nv_bfloat162(
                    __float2bfloat16(v0 - __bfloat162float(h0)),
                    __float2bfloat16(v1 - __bfloat162float(h1)));
                *(__nv_bfloat162*)&Cl[(size_t)rowB * N + col] = __nv_bfloat162(
                    __float2bfloat16(v2 - __bfloat162float(h2)),
                    __float2bfloat16(v3 - __bfloat162float(h3)));
            }
        }
    }
}

// ---------------------------------------------------------------------------
// Kernel wrappers
// ---------------------------------------------------------------------------
__global__ __launch_bounds__(256, 1)
void proj_qkv(const __nv_bfloat16* __restrict__ Eh, const __nv_bfloat16* __restrict__ El,
              const __nv_bfloat16* __restrict__ Wqh, const __nv_bfloat16* __restrict__ Wql,
              const __nv_bfloat16* __restrict__ Wkh, const __nv_bfloat16* __restrict__ Wkl,
              const __nv_bfloat16* __restrict__ Wvh, const __nv_bfloat16* __restrict__ Wvl,
              const float* __restrict__ bq, const float* __restrict__ bk,
              const float* __restrict__ bv,
              __nv_bfloat16* __restrict__ Qh, __nv_bfloat16* __restrict__ Ql,
              __nv_bfloat16* __restrict__ Kh, __nv_bfloat16* __restrict__ Kl,
              __nv_bfloat16* __restrict__ VtH, __nv_bfloat16* __restrict__ VtL)
{
    extern __shared__ char smem[];
    const int z = blockIdx.z;
    const __nv_bfloat16* Bh = (z == 0) ? Wqh : (z == 1) ? Wkh : Wvh;
    const __nv_bfloat16* Bl = (z == 0) ? Wql : (z == 1) ? Wkl : Wvl;
    const float* bias       = (z == 0) ? bq  : (z == 1) ? bk  : bv;
    __nv_bfloat16* Ch       = (z == 0) ? Qh  : (z == 1) ? Kh  : VtH;
    __nv_bfloat16* Cl       = (z == 0) ? Ql  : (z == 1) ? Kl  : VtL;
    const int epi = (z == 2) ? 2 : 1;
    gemm3x_body(Eh, El, Bh, Bl, bias, nullptr, Ch, Cl,
                NTOK, DH, DIN, DIN, DIN, 0, epi, smem);
}

__global__ __launch_bounds__(256, 1)
void score_gemm(const __nv_bfloat16* __restrict__ Qh, const __nv_bfloat16* __restrict__ Ql,
                const __nv_bfloat16* __restrict__ Kh, const __nv_bfloat16* __restrict__ Kl,
                float* __restrict__ S)
{
    extern __shared__ char smem[];
    gemm3x_body(Qh, Ql, Kh, Kl, nullptr, S, nullptr, nullptr,
                NTOK, NTOK, DH, DH, DH, 0, 0, smem);
}

// PV unsplit: full K=4096 per CTA, direct fp32 store to out. 128 CTAs = 1 wave.
__global__ __launch_bounds__(256, 1)
void pv_gemm(const __nv_bfloat16* __restrict__ Ph, const __nv_bfloat16* __restrict__ Pl,
             const __nv_bfloat16* __restrict__ VtH, const __nv_bfloat16* __restrict__ VtL,
             float* __restrict__ out)
{
    extern __shared__ char smem[];
    gemm3x_body(Ph, Pl, VtH, VtL, nullptr, out, nullptr, nullptr,
                NTOK, DH, NTOK, NTOK, NTOK, 0, 0, smem);
}

// ---------------------------------------------------------------------------
// Row softmax over S[NTOK, NTOK], writes split bf16 P. 1 CTA/row.
// Coalesced vectorized I/O: block-strided float4 loads / uint2 plane stores.
// ---------------------------------------------------------------------------
__global__ __launch_bounds__(256)
void softmax_split(const float* __restrict__ S,
                   __nv_bfloat16* __restrict__ Ph, __nv_bfloat16* __restrict__ Pl)
{
    const int row = blockIdx.x;
    const float* p = S + (size_t)row * NTOK;
    const int tid = threadIdx.x;

    float vals[16];
    float m = -CUDART_INF_F;
    #pragma unroll
    for (int i = 0; i < 4; i++) {
        float4 v = *(const float4*)(p + tid * 4 + i * 1024);
        vals[i * 4 + 0] = v.x; vals[i * 4 + 1] = v.y;
        vals[i * 4 + 2] = v.z; vals[i * 4 + 3] = v.w;
        m = fmaxf(m, fmaxf(fmaxf(v.x, v.y), fmaxf(v.z, v.w)));
    }

    __shared__ float red[8];
    #pragma unroll
    for (int o = 16; o > 0; o >>= 1)
        m = fmaxf(m, __shfl_xor_sync(0xffffffffu, m, o));
    if ((tid & 31) == 0) red[tid >> 5] = m;
    __syncthreads();
    if (tid < 32) {
        float x = (tid < 8) ? red[tid] : -CUDART_INF_F;
        #pragma unroll
        for (int o = 4; o > 0; o >>= 1)
            x = fmaxf(x, __shfl_xor_sync(0xffffffffu, x, o));
        if (tid == 0) red[0] = x;
    }
    __syncthreads();
    m = red[0];
    __syncthreads();

    float s = 0.0f;
    #pragma unroll
    for (int i = 0; i < 16; i++) {
        vals[i] = __expf(vals[i] - m);
        s += vals[i];
    }
    #pragma unroll
    for (int o = 16; o > 0; o >>= 1)
        s += __shfl_xor_sync(0xffffffffu, s, o);
    if ((tid & 31) == 0) red[tid >> 5] = s;
    __syncthreads();
    if (tid < 32) {
        float x = (tid < 8) ? red[tid] : 0.0f;
        #pragma unroll
        for (int o = 4; o > 0; o >>= 1)
            x += __shfl_xor_sync(0xffffffffu, x, o);
        if (tid == 0) red[0] = x;
    }
    __syncthreads();
    const float inv = 1.0f / red[0];

    __nv_bfloat16* phb = Ph + (size_t)row * NTOK;
    __nv_bfloat16* plb = Pl + (size_t)row * NTOK;
    #pragma unroll
    for (int i = 0; i < 4; i++) {
        float pv0 = vals[i * 4 + 0] * inv;
        float pv1 = vals[i * 4 + 1] * inv;
        float pv2 = vals[i * 4 + 2] * inv;
        float pv3 = vals[i * 4 + 3] * inv;
        __nv_bfloat16 h0 = __float2bfloat16(pv0);
        __nv_bfloat16 h1 = __float2bfloat16(pv1);
        __nv_bfloat16 h2 = __float2bfloat16(pv2);
        __nv_bfloat16 h3 = __float2bfloat16(pv3);
        __nv_bfloat162 hA(h0, h1), hB(h2, h3);
        __nv_bfloat162 lA(__float2bfloat16(pv0 - __bfloat162float(h0)),
                          __float2bfloat16(pv1 - __bfloat162float(h1)));
        __nv_bfloat162 lB(__float2bfloat16(pv2 - __bfloat162float(h2)),
                          __float2bfloat16(pv3 - __bfloat162float(h3)));
        *(uint2*)(phb + tid * 4 + i * 1024) =
            make_uint2(*(uint32_t*)&hA, *(uint32_t*)&hB);
        *(uint2*)(plb + tid * 4 + i * 1024) =
            make_uint2(*(uint32_t*)&lA, *(uint32_t*)&lB);
    }
}

// ---------------------------------------------------------------------------
// Host launch
// ---------------------------------------------------------------------------
extern "C" void kernel_launch(void* const* d_in, const int* in_sizes, int n_in,
                              void* d_out, int out_size)
{
    const float* embs = (const float*)d_in[0];
    const float* Wq   = (const float*)d_in[1];
    const float* bq   = (const float*)d_in[2];
    const float* Wk   = (const float*)d_in[3];
    const float* bk   = (const float*)d_in[4];
    const float* Wv   = (const float*)d_in[5];
    const float* bv   = (const float*)d_in[6];
    float* out = (float*)d_out;

    __nv_bfloat16 *Eh, *El, *Wqh, *Wql, *Wkh, *Wkl, *Wvh, *Wvl;
    __nv_bfloat16 *Qh, *Ql, *Kh, *Kl, *VtH, *VtL, *Ph, *Pl;
    float *S;
    cudaGetSymbolAddress((void**)&Eh, g_Eh);   cudaGetSymbolAddress((void**)&El, g_El);
    cudaGetSymbolAddress((void**)&Wqh, g_Wqh); cudaGetSymbolAddress((void**)&Wql, g_Wql);
    cudaGetSymbolAddress((void**)&Wkh, g_Wkh); cudaGetSymbolAddress((void**)&Wkl, g_Wkl);
    cudaGetSymbolAddress((void**)&Wvh, g_Wvh); cudaGetSymbolAddress((void**)&Wvl, g_Wvl);
    cudaGetSymbolAddress((void**)&Qh, g_Qh);   cudaGetSymbolAddress((void**)&Ql, g_Ql);
    cudaGetSymbolAddress((void**)&Kh, g_Kh);   cudaGetSymbolAddress((void**)&Kl, g_Kl);
    cudaGetSymbolAddress((void**)&VtH, g_VtH); cudaGetSymbolAddress((void**)&VtL, g_VtL);
    cudaGetSymbolAddress((void**)&S, g_S);
    cudaGetSymbolAddress((void**)&Ph, g_Ph);   cudaGetSymbolAddress((void**)&Pl, g_Pl);

    cudaFuncSetAttribute(proj_qkv,   cudaFuncAttributeMaxDynamicSharedMemorySize, SMEM_BYTES);
    cudaFuncSetAttribute(score_gemm, cudaFuncAttributeMaxDynamicSharedMemorySize, SMEM_BYTES);
    cudaFuncSetAttribute(pv_gemm,    cudaFuncAttributeMaxDynamicSharedMemorySize, SMEM_BYTES);

    // 1) hi/lo splits — single launch, z selects tensor (wide grid for BW)
    dim3 g_split(512, 1, 4);
    split_all<<<g_split, 256>>>((const float4*)embs, (const float4*)Wq,
                                (const float4*)Wk, (const float4*)Wv,
                                (__nv_bfloat162*)Eh, (__nv_bfloat162*)El,
                                (__nv_bfloat162*)Wqh, (__nv_bfloat162*)Wql,
                                (__nv_bfloat162*)Wkh, (__nv_bfloat162*)Wkl,
                                (__nv_bfloat162*)Wvh, (__nv_bfloat162*)Wvl);

    // 2) Q/K/V projections in ONE launch (384 CTAs)
    dim3 g_proj(DH / 128, NTOK / 128, 3);
    proj_qkv<<<g_proj, 256, SMEM_BYTES>>>(Eh, El, Wqh, Wql, Wkh, Wkl, Wvh, Wvl,
                                          bq, bk, bv, Qh, Ql, Kh, Kl, VtH, VtL);

    // 3) scores S = Q @ K^T (1024 CTAs)
    dim3 g_s(NTOK / 128, NTOK / 128);
    score_gemm<<<g_s, 256, SMEM_BYTES>>>(Qh, Ql, Kh, Kl, S);

    // 4) softmax + P split (coalesced vectorized I/O)
    softmax_split<<<NTOK, 256>>>(S, Ph, Pl);

    // 5) out = P @ V, unsplit K (128 CTAs, one wave, no reduce)
    dim3 g_pv(DH / 128, NTOK / 128);
    pv_gemm<<<g_pv, 256, SMEM_BYTES>>>(Ph, Pl, VtH, VtL, out);
}

// round 17
// speedup vs baseline: 1.5242x; 1.5242x over previous
#include <cuda_runtime.h>
#include <cuda_bf16.h>
#include <cstdint>
#include <math_constants.h>

#define NTOK 4096
#define DIN  1024
#define DH   512

// ---------------------------------------------------------------------------
// Scratch (__device__ globals; no allocation allowed)
// ---------------------------------------------------------------------------
__device__ __nv_bfloat16 g_Eh[(size_t)NTOK * DIN];
__device__ __nv_bfloat16 g_El[(size_t)NTOK * DIN];
__device__ __nv_bfloat16 g_Wqh[(size_t)DH * DIN];
__device__ __nv_bfloat16 g_Wql[(size_t)DH * DIN];
__device__ __nv_bfloat16 g_Wkh[(size_t)DH * DIN];
__device__ __nv_bfloat16 g_Wkl[(size_t)DH * DIN];
__device__ __nv_bfloat16 g_Wvh[(size_t)DH * DIN];
__device__ __nv_bfloat16 g_Wvl[(size_t)DH * DIN];
__device__ __nv_bfloat16 g_Qh[(size_t)NTOK * DH];
__device__ __nv_bfloat16 g_Ql[(size_t)NTOK * DH];
__device__ __nv_bfloat16 g_Kh[(size_t)NTOK * DH];
__device__ __nv_bfloat16 g_Kl[(size_t)NTOK * DH];
__device__ __nv_bfloat16 g_VtH[(size_t)DH * NTOK];
__device__ __nv_bfloat16 g_VtL[(size_t)DH * NTOK];
__device__ float         g_S[(size_t)NTOK * NTOK];
__device__ __nv_bfloat16 g_Ph[(size_t)NTOK * NTOK];
__device__ __nv_bfloat16 g_Pl[(size_t)NTOK * NTOK];

// ---------------------------------------------------------------------------
// PTX helpers (sm_80-level: valid under compute_103 virtual arch)
// ---------------------------------------------------------------------------
__device__ __forceinline__ uint32_t smem_u32(const void* p) {
    uint32_t a;
    asm("{ .reg .u64 t; cvta.to.shared.u64 t, %1; cvt.u32.u64 %0, t; }"
        : "=r"(a) : "l"(p));
    return a;
}

__device__ __forceinline__ void cp16(uint32_t dst, const void* src) {
    asm volatile("cp.async.cg.shared.global [%0], [%1], 16;"
                 :: "r"(dst), "l"(src) : "memory");
}
#define CP_COMMIT() asm volatile("cp.async.commit_group;" ::: "memory")
#define CP_WAIT(n)  asm volatile("cp.async.wait_group %0;" :: "n"(n) : "memory")

#define LDSM4(r0, r1, r2, r3, addr)                                            \
    asm volatile("ldmatrix.sync.aligned.m8n8.x4.shared.b16 {%0,%1,%2,%3}, [%4];" \
                 : "=r"(r0), "=r"(r1), "=r"(r2), "=r"(r3) : "r"(addr))

#define MMA_BF16(c, a, b0, b1)                                                 \
    asm volatile("mma.sync.aligned.m16n8k16.row.col.f32.bf16.bf16.f32 "        \
                 "{%0,%1,%2,%3}, {%4,%5,%6,%7}, {%8,%9}, {%0,%1,%2,%3};"       \
                 : "+f"((c)[0]), "+f"((c)[1]), "+f"((c)[2]), "+f"((c)[3])      \
                 : "r"((a)[0]), "r"((a)[1]), "r"((a)[2]), "r"((a)[3]),         \
                   "r"(b0), "r"(b1))

__device__ __forceinline__ uint32_t sw(uint32_t off) {
    return off ^ ((off >> 3) & 0x70);
}

// ---------------------------------------------------------------------------
// hi/lo split conversion (fp32 -> bf16 hi + bf16 lo), one z-indexed launch
// ---------------------------------------------------------------------------
__device__ __forceinline__ void split4(float4 v, __nv_bfloat162* h, __nv_bfloat162* l,
                                       int i)
{
    __nv_bfloat16 hx = __float2bfloat16(v.x);
    __nv_bfloat16 hy = __float2bfloat16(v.y);
    __nv_bfloat16 hz = __float2bfloat16(v.z);
    __nv_bfloat16 hw = __float2bfloat16(v.w);
    h[2 * i + 0] = __nv_bfloat162(hx, hy);
    h[2 * i + 1] = __nv_bfloat162(hz, hw);
    l[2 * i + 0] = __nv_bfloat162(__float2bfloat16(v.x - __bfloat162float(hx)),
                                  __float2bfloat16(v.y - __bfloat162float(hy)));
    l[2 * i + 1] = __nv_bfloat162(__float2bfloat16(v.z - __bfloat162float(hz)),
                                  __float2bfloat16(v.w - __bfloat162float(hw)));
}

__global__ void split_all(const float4* __restrict__ embs,
                          const float4* __restrict__ Wq,
                          const float4* __restrict__ Wk,
                          const float4* __restrict__ Wv,
                          __nv_bfloat162* __restrict__ eh, __nv_bfloat162* __restrict__ el,
                          __nv_bfloat162* __restrict__ qh, __nv_bfloat162* __restrict__ ql,
                          __nv_bfloat162* __restrict__ kh, __nv_bfloat162* __restrict__ kl,
                          __nv_bfloat162* __restrict__ vh, __nv_bfloat162* __restrict__ vl)
{
    const int z = blockIdx.z;
    const float4* x;
    __nv_bfloat162 *h, *l;
    int n4;
    if (z == 0)      { x = embs; h = eh; l = el; n4 = NTOK * DIN / 4; }
    else if (z == 1) { x = Wq;   h = qh; l = ql; n4 = DH * DIN / 4; }
    else if (z == 2) { x = Wk;   h = kh; l = kl; n4 = DH * DIN / 4; }
    else             { x = Wv;   h = vh; l = vl; n4 = DH * DIN / 4; }
    for (int i = blockIdx.x * blockDim.x + threadIdx.x; i < n4;
         i += gridDim.x * blockDim.x)
        split4(x[i], h, l, i);
}

// ---------------------------------------------------------------------------
// GEMM body (round-11 exact): C = Ah·Bh^T + Ah·Bl^T + Al·Bh^T over K from kbase.
// 3-stage cp.async pipeline, ONE __syncthreads per chunk, register
// double-buffered fragments. CTA 128x128, 8 warps (4x2), warp tile 32x64.
// epi: 0 = fp32 C, 1 = split (Ch,Cl) [M,N], 2 = split transposed [N,M] (scalar)
// ---------------------------------------------------------------------------
#define KCH 64
#define TILE_BYTES  16384          // 128 rows x 128B
#define STAGE_BYTES 65536          // Ah | Al | Bh | Bl
#define NSTAGE 3
#define SMEM_BYTES  (NSTAGE * STAGE_BYTES)   // 192 KB

__device__ __forceinline__ void load_tile(uint32_t sbase, const __nv_bfloat16* g,
                                          int ld, int row0, int k0, int tid)
{
    const char* gp = (const char*)(g + (size_t)row0 * ld + k0);
    size_t ldb = (size_t)ld * 2;
    #pragma unroll
    for (int i = 0; i < 4; i++) {
        int idx = tid + i * 256;
        int r = idx >> 3, j = idx & 7;
        uint32_t off = (uint32_t)(r * 128 + j * 16);
        cp16(sbase + sw(off), gp + (size_t)r * ldb + j * 16);
    }
}

__device__ __forceinline__ void gemm3x_body(
    const __nv_bfloat16* __restrict__ Ah, const __nv_bfloat16* __restrict__ Al,
    const __nv_bfloat16* __restrict__ Bh, const __nv_bfloat16* __restrict__ Bl,
    const float* __restrict__ bias,
    float* __restrict__ Cf,
    __nv_bfloat16* __restrict__ Ch, __nv_bfloat16* __restrict__ Cl,
    int M, int N, int K, int ldA, int ldB, int kbase, int epi, char* smem)
{
    const uint32_t sb = smem_u32(smem);

    const int tid  = threadIdx.x;
    const int wid  = tid >> 5;
    const int lane = tid & 31;
    const int wm   = wid >> 1;          // 0..3
    const int wn   = wid & 1;           // 0..1
    const int bm   = blockIdx.y * 128;
    const int bn   = blockIdx.x * 128;

    float acc[2][8][4];
    #pragma unroll
    for (int i = 0; i < 2; i++)
        #pragma unroll
        for (int j = 0; j < 8; j++)
            #pragma unroll
            for (int t = 0; t < 4; t++) acc[i][j][t] = 0.0f;

    const int KC = K / KCH;

    const int a_row = wm * 32 + (lane & 15);
    const int a_seg = (lane >> 4);
    const int b_row = wn * 64 + (lane & 7) + ((lane >> 4) << 3);
    const int b_seg = ((lane >> 3) & 1);

    auto load_chunk = [&](uint32_t stg, int c) {
        const int k0 = kbase + c * KCH;
        load_tile(stg,                  Ah, ldA, bm, k0, tid);
        load_tile(stg + TILE_BYTES,     Al, ldA, bm, k0, tid);
        load_tile(stg + 2 * TILE_BYTES, Bh, ldB, bn, k0, tid);
        load_tile(stg + 3 * TILE_BYTES, Bl, ldB, bn, k0, tid);
    };

    // prologue: 2 chunks in flight
    load_chunk(sb, 0);
    CP_COMMIT();
    if (KC > 1) load_chunk(sb + STAGE_BYTES, 1);
    CP_COMMIT();

    // Double-buffered fragments
    uint32_t aH[2][2][4], aL[2][2][4], bHf[2][4][4], bLf[2][4][4];

    for (int c = 0; c < KC; c++) {
        if (c + 1 < KC) { CP_WAIT(1); } else { CP_WAIT(0); }
        __syncthreads();    // stage c%3 ready; everyone done reading stage (c+2)%3

        // loads for chunk c+2 into stage (c+2)%3 — overlap the MMAs below
        if (c + 2 < KC)
            load_chunk(sb + (uint32_t)((c + 2) % NSTAGE) * STAGE_BYTES, c + 2);
        CP_COMMIT();

        const uint32_t stg = sb + (uint32_t)(c % NSTAGE) * STAGE_BYTES;
        const uint32_t saH = stg;
        const uint32_t saL = stg + TILE_BYTES;
        const uint32_t sbH = stg + 2 * TILE_BYTES;
        const uint32_t sbL = stg + 3 * TILE_BYTES;

        // preload ks=0 fragments into buffer 0
        {
            #pragma unroll
            for (int mi = 0; mi < 2; mi++) {
                uint32_t so = sw((uint32_t)((a_row + mi * 16) * 128 + a_seg * 16));
                LDSM4(aH[0][mi][0], aH[0][mi][1], aH[0][mi][2], aH[0][mi][3], saH + so);
                LDSM4(aL[0][mi][0], aL[0][mi][1], aL[0][mi][2], aL[0][mi][3], saL + so);
            }
            #pragma unroll
            for (int ng = 0; ng < 4; ng++) {
                uint32_t so = sw((uint32_t)((b_row + ng * 16) * 128 + b_seg * 16));
                LDSM4(bHf[0][ng][0], bHf[0][ng][1], bHf[0][ng][2], bHf[0][ng][3], sbH + so);
                LDSM4(bLf[0][ng][0], bLf[0][ng][1], bLf[0][ng][2], bLf[0][ng][3], sbL + so);
            }
        }

        #pragma unroll
        for (int ks = 0; ks < 4; ks++) {
            const int cur = ks & 1;
            const int nxt = cur ^ 1;
            if (ks < 3) {
                // issue next ks's LDSMs before this ks's MMAs
                #pragma unroll
                for (int mi = 0; mi < 2; mi++) {
                    uint32_t so = sw((uint32_t)((a_row + mi * 16) * 128 +
                                                ((ks + 1) * 2 + a_seg) * 16));
                    LDSM4(aH[nxt][mi][0], aH[nxt][mi][1], aH[nxt][mi][2], aH[nxt][mi][3],
                          saH + so);
                    LDSM4(aL[nxt][mi][0], aL[nxt][mi][1], aL[nxt][mi][2], aL[nxt][mi][3],
                          saL + so);
                }
                #pragma unroll
                for (int ng = 0; ng < 4; ng++) {
                    uint32_t so = sw((uint32_t)((b_row + ng * 16) * 128 +
                                                ((ks + 1) * 2 + b_seg) * 16));
                    LDSM4(bHf[nxt][ng][0], bHf[nxt][ng][1], bHf[nxt][ng][2], bHf[nxt][ng][3],
                          sbH + so);
                    LDSM4(bLf[nxt][ng][0], bLf[nxt][ng][1], bLf[nxt][ng][2], bLf[nxt][ng][3],
                          sbL + so);
                }
            }
            #pragma unroll
            for (int mi = 0; mi < 2; mi++)
                #pragma unroll
                for (int nj = 0; nj < 8; nj++) {
                    const int ng = nj >> 1, hp = (nj & 1) << 1;
                    MMA_BF16(acc[mi][nj], aH[cur][mi], bHf[cur][ng][hp], bHf[cur][ng][hp + 1]);
                }
            #pragma unroll
            for (int mi = 0; mi < 2; mi++)
                #pragma unroll
                for (int nj = 0; nj < 8; nj++) {
                    const int ng = nj >> 1, hp = (nj & 1) << 1;
                    MMA_BF16(acc[mi][nj], aH[cur][mi], bLf[cur][ng][hp], bLf[cur][ng][hp + 1]);
                }
            #pragma unroll
            for (int mi = 0; mi < 2; mi++)
                #pragma unroll
                for (int nj = 0; nj < 8; nj++) {
                    const int ng = nj >> 1, hp = (nj & 1) << 1;
                    MMA_BF16(acc[mi][nj], aL[cur][mi], bHf[cur][ng][hp], bHf[cur][ng][hp + 1]);
                }
        }
        // no trailing sync: next iteration's top sync protects stage reuse
    }

    // ---------------- epilogue ----------------
    const int r0  = (lane >> 2);
    const int cth = 2 * (lane & 3);
    #pragma unroll
    for (int mi = 0; mi < 2; mi++) {
        #pragma unroll
        for (int nj = 0; nj < 8; nj++) {
            const int col = bn + wn * 64 + nj * 8 + cth;
            float v0 = acc[mi][nj][0], v1 = acc[mi][nj][1];
            float v2 = acc[mi][nj][2], v3 = acc[mi][nj][3];
            if (bias) {
                float b0 = bias[col], b1 = bias[col + 1];
                v0 += b0; v1 += b1; v2 += b0; v3 += b1;
            }
            const int rowA = bm + wm * 32 + mi * 16 + r0;
            const int rowB = rowA + 8;
            if (epi == 0) {
                *(float2*)&Cf[(size_t)rowA * N + col] = make_float2(v0, v1);
                *(float2*)&Cf[(size_t)rowB * N + col] = make_float2(v2, v3);
            } else {
                __nv_bfloat16 h0 = __float2bfloat16(v0);
                __nv_bfloat16 h1 = __float2bfloat16(v1);
                __nv_bfloat16 h2 = __float2bfloat16(v2);
                __nv_bfloat16 h3 = __float2bfloat16(v3);
                __nv_bfloat16 l0 = __float2bfloat16(v0 - __bfloat162float(h0));
                __nv_bfloat16 l1 = __float2bfloat16(v1 - __bfloat162float(h1));
                __nv_bfloat16 l2 = __float2bfloat16(v2 - __bfloat162float(h2));
                __nv_bfloat16 l3 = __float2bfloat16(v3 - __bfloat162float(h3));
                if (epi == 1) {
                    *(__nv_bfloat162*)&Ch[(size_t)rowA * N + col] = __nv_bfloat162(h0, h1);
                    *(__nv_bfloat162*)&Ch[(size_t)rowB * N + col] = __nv_bfloat162(h2, h3);
                    *(__nv_bfloat162*)&Cl[(size_t)rowA * N + col] = __nv_bfloat162(l0, l1);
                    *(__nv_bfloat162*)&Cl[(size_t)rowB * N + col] = __nv_bfloat162(l2, l3);
                } else {
                    Ch[(size_t)col * M + rowA]       = h0;
                    Ch[(size_t)(col + 1) * M + rowA] = h1;
                    Ch[(size_t)col * M + rowB]       = h2;
                    Ch[(size_t)(col + 1) * M + rowB] = h3;
                    Cl[(size_t)col * M + rowA]       = l0;
                    Cl[(size_t)(col + 1) * M + rowA] = l1;
                    Cl[(size_t)col * M + rowB]       = l2;
                    Cl[(size_t)(col + 1) * M + rowB] = l3;
                }
            }
        }
    }
}

// ---------------------------------------------------------------------------
// Kernel wrappers
// ---------------------------------------------------------------------------
__global__ __launch_bounds__(256, 1)
void proj_qkv(const __nv_bfloat16* __restrict__ Eh, const __nv_bfloat16* __restrict__ El,
              const __nv_bfloat16* __restrict__ Wqh, const __nv_bfloat16* __restrict__ Wql,
              const __nv_bfloat16* __restrict__ Wkh, const __nv_bfloat16* __restrict__ Wkl,
              const __nv_bfloat16* __restrict__ Wvh, const __nv_bfloat16* __restrict__ Wvl,
              const float* __restrict__ bq, const float* __restrict__ bk,
              const float* __restrict__ bv,
              __nv_bfloat16* __restrict__ Qh, __nv_bfloat16* __restrict__ Ql,
              __nv_bfloat16* __restrict__ Kh, __nv_bfloat16* __restrict__ Kl,
              __nv_bfloat16* __restrict__ VtH, __nv_bfloat16* __restrict__ VtL)
{
    extern __shared__ char smem[];
    const int z = blockIdx.z;
    const __nv_bfloat16* Bh = (z == 0) ? Wqh : (z == 1) ? Wkh : Wvh;
    const __nv_bfloat16* Bl = (z == 0) ? Wql : (z == 1) ? Wkl : Wvl;
    const float* bias       = (z == 0) ? bq  : (z == 1) ? bk  : bv;
    __nv_bfloat16* Ch       = (z == 0) ? Qh  : (z == 1) ? Kh  : VtH;
    __nv_bfloat16* Cl       = (z == 0) ? Ql  : (z == 1) ? Kl  : VtL;
    const int epi = (z == 2) ? 2 : 1;
    gemm3x_body(Eh, El, Bh, Bl, bias, nullptr, Ch, Cl,
                NTOK, DH, DIN, DIN, DIN, 0, epi, smem);
}

__global__ __launch_bounds__(256, 1)
void score_gemm(const __nv_bfloat16* __restrict__ Qh, const __nv_bfloat16* __restrict__ Ql,
                const __nv_bfloat16* __restrict__ Kh, const __nv_bfloat16* __restrict__ Kl,
                float* __restrict__ S)
{
    extern __shared__ char smem[];
    gemm3x_body(Qh, Ql, Kh, Kl, nullptr, S, nullptr, nullptr,
                NTOK, NTOK, DH, DH, DH, 0, 0, smem);
}

// PV unsplit: full K=4096 per CTA, direct fp32 store to out. 128 CTAs = 1 wave.
__global__ __launch_bounds__(256, 1)
void pv_gemm(const __nv_bfloat16* __restrict__ Ph, const __nv_bfloat16* __restrict__ Pl,
             const __nv_bfloat16* __restrict__ VtH, const __nv_bfloat16* __restrict__ VtL,
             float* __restrict__ out)
{
    extern __shared__ char smem[];
    gemm3x_body(Ph, Pl, VtH, VtL, nullptr, out, nullptr, nullptr,
                NTOK, DH, NTOK, NTOK, NTOK, 0, 0, smem);
}

// ---------------------------------------------------------------------------
// Row softmax over S[NTOK, NTOK], writes split bf16 P. 1 CTA/row.
// Coalesced vectorized I/O: block-strided float4 loads / uint2 plane stores.
// ---------------------------------------------------------------------------
__global__ __launch_bounds__(256)
void softmax_split(const float* __restrict__ S,
                   __nv_bfloat16* __restrict__ Ph, __nv_bfloat16* __restrict__ Pl)
{
    const int row = blockIdx.x;
    const float* p = S + (size_t)row * NTOK;
    const int tid = threadIdx.x;

    float vals[16];
    float m = -CUDART_INF_F;
    #pragma unroll
    for (int i = 0; i < 4; i++) {
        float4 v = *(const float4*)(p + tid * 4 + i * 1024);
        vals[i * 4 + 0] = v.x; vals[i * 4 + 1] = v.y;
        vals[i * 4 + 2] = v.z; vals[i * 4 + 3] = v.w;
        m = fmaxf(m, fmaxf(fmaxf(v.x, v.y), fmaxf(v.z, v.w)));
    }

    __shared__ float red[8];
    #pragma unroll
    for (int o = 16; o > 0; o >>= 1)
        m = fmaxf(m, __shfl_xor_sync(0xffffffffu, m, o));
    if ((tid & 31) == 0) red[tid >> 5] = m;
    __syncthreads();
    if (tid < 32) {
        float x = (tid < 8) ? red[tid] : -CUDART_INF_F;
        #pragma unroll
        for (int o = 4; o > 0; o >>= 1)
            x = fmaxf(x, __shfl_xor_sync(0xffffffffu, x, o));
        if (tid == 0) red[0] = x;
    }
    __syncthreads();
    m = red[0];
    __syncthreads();

    float s = 0.0f;
    #pragma unroll
    for (int i = 0; i < 16; i++) {
        vals[i] = __expf(vals[i] - m);
        s += vals[i];
    }
    #pragma unroll
    for (int o = 16; o > 0; o >>= 1)
        s += __shfl_xor_sync(0xffffffffu, s, o);
    if ((tid & 31) == 0) red[tid >> 5] = s;
    __syncthreads();
    if (tid < 32) {
        float x = (tid < 8) ? red[tid] : 0.0f;
        #pragma unroll
        for (int o = 4; o > 0; o >>= 1)
            x += __shfl_xor_sync(0xffffffffu, x, o);
        if (tid == 0) red[0] = x;
    }
    __syncthreads();
    const float inv = 1.0f / red[0];

    __nv_bfloat16* phb = Ph + (size_t)row * NTOK;
    __nv_bfloat16* plb = Pl + (size_t)row * NTOK;
    #pragma unroll
    for (int i = 0; i < 4; i++) {
        float pv0 = vals[i * 4 + 0] * inv;
        float pv1 = vals[i * 4 + 1] * inv;
        float pv2 = vals[i * 4 + 2] * inv;
        float pv3 = vals[i * 4 + 3] * inv;
        __nv_bfloat16 h0 = __float2bfloat16(pv0);
        __nv_bfloat16 h1 = __float2bfloat16(pv1);
        __nv_bfloat16 h2 = __float2bfloat16(pv2);
        __nv_bfloat16 h3 = __float2bfloat16(pv3);
        __nv_bfloat162 hA(h0, h1), hB(h2, h3);
        __nv_bfloat162 lA(__float2bfloat16(pv0 - __bfloat162float(h0)),
                          __float2bfloat16(pv1 - __bfloat162float(h1)));
        __nv_bfloat162 lB(__float2bfloat16(pv2 - __bfloat162float(h2)),
                          __float2bfloat16(pv3 - __bfloat162float(h3)));
        *(uint2*)(phb + tid * 4 + i * 1024) =
            make_uint2(*(uint32_t*)&hA, *(uint32_t*)&hB);
        *(uint2*)(plb + tid * 4 + i * 1024) =
            make_uint2(*(uint32_t*)&lA, *(uint32_t*)&lB);
    }
}

// ---------------------------------------------------------------------------
// Host launch
// ---------------------------------------------------------------------------
extern "C" void kernel_launch(void* const* d_in, const int* in_sizes, int n_in,
                              void* d_out, int out_size)
{
    const float* embs = (const float*)d_in[0];
    const float* Wq   = (const float*)d_in[1];
    const float* bq   = (const float*)d_in[2];
    const float* Wk   = (const float*)d_in[3];
    const float* bk   = (const float*)d_in[4];
    const float* Wv   = (const float*)d_in[5];
    const float* bv   = (const float*)d_in[6];
    float* out = (float*)d_out;

    __nv_bfloat16 *Eh, *El, *Wqh, *Wql, *Wkh, *Wkl, *Wvh, *Wvl;
    __nv_bfloat16 *Qh, *Ql, *Kh, *Kl, *VtH, *VtL, *Ph, *Pl;
    float *S;
    cudaGetSymbolAddress((void**)&Eh, g_Eh);   cudaGetSymbolAddress((void**)&El, g_El);
    cudaGetSymbolAddress((void**)&Wqh, g_Wqh); cudaGetSymbolAddress((void**)&Wql, g_Wql);
    cudaGetSymbolAddress((void**)&Wkh, g_Wkh); cudaGetSymbolAddress((void**)&Wkl, g_Wkl);
    cudaGetSymbolAddress((void**)&Wvh, g_Wvh); cudaGetSymbolAddress((void**)&Wvl, g_Wvl);
    cudaGetSymbolAddress((void**)&Qh, g_Qh);   cudaGetSymbolAddress((void**)&Ql, g_Ql);
    cudaGetSymbolAddress((void**)&Kh, g_Kh);   cudaGetSymbolAddress((void**)&Kl, g_Kl);
    cudaGetSymbolAddress((void**)&VtH, g_VtH); cudaGetSymbolAddress((void**)&VtL, g_VtL);
    cudaGetSymbolAddress((void**)&S, g_S);
    cudaGetSymbolAddress((void**)&Ph, g_Ph);   cudaGetSymbolAddress((void**)&Pl, g_Pl);

    cudaFuncSetAttribute(proj_qkv,   cudaFuncAttributeMaxDynamicSharedMemorySize, SMEM_BYTES);
    cudaFuncSetAttribute(score_gemm, cudaFuncAttributeMaxDynamicSharedMemorySize, SMEM_BYTES);
    cudaFuncSetAttribute(pv_gemm,    cudaFuncAttributeMaxDynamicSharedMemorySize, SMEM_BYTES);

    // 1) hi/lo splits — single launch, z selects tensor (wide grid for BW)
    dim3 g_split(512, 1, 4);
    split_all<<<g_split, 256>>>((const float4*)embs, (const float4*)Wq,
                                (const float4*)Wk, (const float4*)Wv,
                                (__nv_bfloat162*)Eh, (__nv_bfloat162*)El,
                                (__nv_bfloat162*)Wqh, (__nv_bfloat162*)Wql,
                                (__nv_bfloat162*)Wkh, (__nv_bfloat162*)Wkl,
                                (__nv_bfloat162*)Wvh, (__nv_bfloat162*)Wvl);

    // 2) Q/K/V projections in ONE launch (384 CTAs)
    dim3 g_proj(DH / 128, NTOK / 128, 3);
    proj_qkv<<<g_proj, 256, SMEM_BYTES>>>(Eh, El, Wqh, Wql, Wkh, Wkl, Wvh, Wvl,
                                          bq, bk, bv, Qh, Ql, Kh, Kl, VtH, VtL);

    // 3) scores S = Q @ K^T (1024 CTAs)
    dim3 g_s(NTOK / 128, NTOK / 128);
    score_gemm<<<g_s, 256, SMEM_BYTES>>>(Qh, Ql, Kh, Kl, S);

    // 4) softmax + P split (coalesced vectorized I/O)
    softmax_split<<<NTOK, 256>>>(S, Ph, Pl);

    // 5) out = P @ V, unsplit K (128 CTAs, one wave, no reduce)
    dim3 g_pv(DH / 128, NTOK / 128);
    pv_gemm<<<g_pv, 256, SMEM_BYTES>>>(Ph, Pl, VtH, VtL, out);
}